// round 14
// baseline (speedup 1.0000x reference)
#include <cuda_runtime.h>
#include <math.h>
#include <stdint.h>

// ---------------- problem constants ----------------
#define B_    4
#define LQ_   512
#define LKV_  8192
#define QDIM  1024
#define KVDIM 512
#define CH    256      // QK_CH == V_CH == 256 (GEMM N)
#define HEADS 8
#define DH    32
#define QSCALE 0.2550348587f   // (1/sqrt(32)) * log2(e)
#define NSPLIT 2               // KV-axis split for attention

// ---------------- scratch ----------------
__device__ float g_hsn [B_*LQ_*QDIM];
__device__ float g_inpn[B_*LKV_*KVDIM];
__device__ float g_q  [B_*LQ_*CH];
__device__ float g_k  [B_*LKV_*CH];
__device__ float g_v  [B_*LKV_*CH];
__device__ float g_wq [QDIM*CH];
__device__ float g_wk [KVDIM*CH];
__device__ float g_wv [KVDIM*CH];
__device__ float g_opart[NSPLIT*B_*LQ_*CH];     // unnormalized O partials
__device__ float g_lpart[NSPLIT*B_*LQ_*HEADS];  // softmax denominators

// ================= helpers (baseline PTX only) =================
__device__ __forceinline__ uint32_t smem_u32(const void* p){
    uint32_t a; asm("{ .reg .u64 t; cvta.to.shared.u64 t, %1; cvt.u32.u64 %0, t; }" : "=r"(a) : "l"(p)); return a;
}
__device__ __forceinline__ uint32_t f2tf32(float f){
    uint32_t t; asm("cvt.rna.tf32.f32 %0, %1;" : "=r"(t) : "f"(f)); return t;
}
__device__ __forceinline__ float fexp2(float x){
    float y; asm("ex2.approx.ftz.f32 %0, %1;" : "=f"(y) : "f"(x)); return y;
}
// pack two f32 -> f16x2 (RNE): upper = hi, lower = lo
// fp16 (10 mantissa bits) quarters the PV quantization error vs bf16; range
// analysis: p = 2^s <= ~2^10 << 65504, |v| <= ~8 -> no overflow; underflow
// only for negligible-weight keys.
__device__ __forceinline__ uint32_t pack_f16(float hi, float lo){
    uint32_t r; asm("cvt.rn.f16x2.f32 %0, %1, %2;" : "=r"(r) : "f"(hi), "f"(lo)); return r;
}
__device__ __forceinline__ void cpa16(uint32_t dst, const void* src){
    asm volatile("cp.async.ca.shared.global [%0], [%1], 16;" :: "r"(dst), "l"(src) : "memory");
}
#define CPA_COMMIT() asm volatile("cp.async.commit_group;" ::: "memory")
#define CPA_WAIT(n)  asm volatile("cp.async.wait_group " #n ";" ::: "memory")

// m16n8k8 tf32 mma: D = A*B + D (A row-major, B col-major)
__device__ __forceinline__ void mma8(float* c, const uint32_t* a, uint32_t b0, uint32_t b1){
    asm volatile("mma.sync.aligned.m16n8k8.row.col.f32.tf32.tf32.f32 "
        "{%0,%1,%2,%3}, {%4,%5,%6,%7}, {%8,%9}, {%0,%1,%2,%3};"
        : "+f"(c[0]), "+f"(c[1]), "+f"(c[2]), "+f"(c[3])
        : "r"(a[0]), "r"(a[1]), "r"(a[2]), "r"(a[3]), "r"(b0), "r"(b1));
}
// m16n8k16 fp16 mma (fp32 accum): D = A*B + D
__device__ __forceinline__ void mma16h(float* c, const uint32_t* a, uint32_t b0, uint32_t b1){
    asm volatile("mma.sync.aligned.m16n8k16.row.col.f32.f16.f16.f32 "
        "{%0,%1,%2,%3}, {%4,%5,%6,%7}, {%8,%9}, {%0,%1,%2,%3};"
        : "+f"(c[0]), "+f"(c[1]), "+f"(c[2]), "+f"(c[3])
        : "r"(a[0]), "r"(a[1]), "r"(a[2]), "r"(a[3]), "r"(b0), "r"(b1));
}

// ---------------- LayerNorm, output RNA-rounded to tf32 ----------------
template<int N>
__global__ __launch_bounds__(256) void ln_kernel(
    const float* __restrict__ x, const float* __restrict__ g,
    const float* __restrict__ b, float* __restrict__ y)
{
    constexpr int T = 256;
    constexpr int PER = N / T;
    const int row = blockIdx.x;
    const float* xr = x + (size_t)row * N;

    float v[PER];
    float s = 0.f, sq = 0.f;
#pragma unroll
    for (int i = 0; i < PER; i++) {
        v[i] = xr[threadIdx.x + i * T];
        s  += v[i];
        sq += v[i] * v[i];
    }
#pragma unroll
    for (int o = 16; o > 0; o >>= 1) {
        s  += __shfl_xor_sync(0xffffffffu, s,  o);
        sq += __shfl_xor_sync(0xffffffffu, sq, o);
    }
    __shared__ float rs[8], rq[8];
    const int warp = threadIdx.x >> 5, lane = threadIdx.x & 31;
    if (lane == 0) { rs[warp] = s; rq[warp] = sq; }
    __syncthreads();
    if (threadIdx.x == 0) {
        float ts = 0.f, tq = 0.f;
#pragma unroll
        for (int i = 0; i < 8; i++) { ts += rs[i]; tq += rq[i]; }
        rs[0] = ts; rq[0] = tq;
    }
    __syncthreads();
    const float mean = rs[0] * (1.f / N);
    const float var  = rq[0] * (1.f / N) - mean * mean;
    const float rstd = rsqrtf(var + 1e-5f);

    float* yr = y + (size_t)row * N;
#pragma unroll
    for (int i = 0; i < PER; i++) {
        const int c = threadIdx.x + i * T;
        const float yv = (v[i] - mean) * rstd * g[c] + b[c];
        yr[c] = __uint_as_float(f2tf32(yv));   // RNA tf32: mma truncation becomes exact
    }
}

// ---------------- weight RNA-rounding (elementwise) ----------------
__global__ void round_w_kernel(const float* __restrict__ w, float* __restrict__ wr, int n)
{
    const int i = blockIdx.x * 256 + threadIdx.x;
    if (i < n) wr[i] = __uint_as_float(f2tf32(w[i]));
}

// ---------------- single-pass tf32 GEMM (unchanged, near its floor) ---------
#define GBM 128
#define GBN 128
#define GBK 16
#define ALD 20
#define WLD 136
#define ASZ (GBM*ALD)
#define WSZ (GBK*WLD)

__global__ void __launch_bounds__(256) gemm_tf32_kernel(
    const float* __restrict__ A, const float* __restrict__ W,
    const float* __restrict__ bias, float* __restrict__ C,
    int M, int K)
{
    __shared__ float sA[2][ASZ];
    __shared__ float sW[2][WSZ];

    const int tid  = threadIdx.x;
    const int wid  = tid >> 5;
    const int lane = tid & 31;
    const int g    = lane >> 2;
    const int tig  = lane & 3;
    const int bm   = blockIdx.x * GBM;
    const int bn   = blockIdx.y * GBN;
    const int wm   = (wid & 3) * 32;
    const int wn   = (wid >> 2) * 64;

#define G_ISSUE(s, nb) do {                                                        \
    const int _k0 = (s) * GBK;                                                     \
    _Pragma("unroll")                                                              \
    for (int i = 0; i < 2; i++) {                                                  \
        const int idx = tid + i * 256;                                             \
        const int ar = idx >> 2, aq4 = (idx & 3) * 4;                              \
        cpa16(smem_u32(&sA[nb][ar*ALD + aq4]), A + (size_t)(bm+ar)*K + _k0 + aq4); \
        const int wr = idx >> 5, wc = (idx & 31) * 4;                              \
        cpa16(smem_u32(&sW[nb][wr*WLD + wc]), W + (size_t)(_k0+wr)*CH + bn + wc);  \
    }                                                                              \
    CPA_COMMIT();                                                                  \
} while (0)

    float cacc[2][8][4];
#pragma unroll
    for (int i = 0; i < 2; i++)
#pragma unroll
        for (int n = 0; n < 8; n++)
#pragma unroll
            for (int r = 0; r < 4; r++) cacc[i][n][r] = 0.f;

    const int NS = K / GBK;
    G_ISSUE(0, 0);

    for (int s = 0; s < NS; s++) {
        const int nb = s & 1;
        if (s < NS - 1) { G_ISSUE(s + 1, (s + 1) & 1); CPA_WAIT(1); }
        else            { CPA_WAIT(0); }
        __syncthreads();

        const uint32_t* uA = (const uint32_t*)sA[nb];
        const uint32_t* uW = (const uint32_t*)sW[nb];

#pragma unroll
        for (int k8 = 0; k8 < 2; k8++) {
            const int kc = k8 * 8 + tig;
            uint32_t af[2][4];
#pragma unroll
            for (int i = 0; i < 2; i++) {
                const int r0 = (wm + i * 16 + g) * ALD;
                const int r1 = (wm + i * 16 + g + 8) * ALD;
                af[i][0] = uA[r0 + kc];     af[i][1] = uA[r1 + kc];
                af[i][2] = uA[r0 + kc + 4]; af[i][3] = uA[r1 + kc + 4];
            }
#pragma unroll
            for (int nf = 0; nf < 8; nf++) {
                const int n = wn + nf * 8 + g;
                const uint32_t b0 = uW[(k8 * 8 + tig) * WLD + n];
                const uint32_t b1 = uW[(k8 * 8 + tig + 4) * WLD + n];
                mma8(cacc[0][nf], af[0], b0, b1);
                mma8(cacc[1][nf], af[1], b0, b1);
            }
        }
        __syncthreads();
    }

#pragma unroll
    for (int i = 0; i < 2; i++) {
#pragma unroll
        for (int n = 0; n < 8; n++) {
            const int col = bn + wn + n * 8 + 2 * tig;
            const float b0 = bias[col], b1 = bias[col + 1];
            const int r0 = bm + wm + i * 16 + g;
            float2 w0, w1;
            w0.x = __uint_as_float(f2tf32(cacc[i][n][0] + b0));
            w0.y = __uint_as_float(f2tf32(cacc[i][n][1] + b1));
            w1.x = __uint_as_float(f2tf32(cacc[i][n][2] + b0));
            w1.y = __uint_as_float(f2tf32(cacc[i][n][3] + b1));
            *(float2*)(C + (size_t)r0 * CH + col)       = w0;
            *(float2*)(C + (size_t)(r0 + 8) * CH + col) = w1;
        }
    }
}

// ================= split-KV attention: tf32 S-phase + fp16 PV =================
// PV trick: tf32 m16n8k8 C-fragment layout == f16 m16n8k16 A-fragment layout,
// so P packs thread-locally (cvt.rn.f16x2) with ZERO shuffles, and k16 halves
// the PV mma count. V is transposed+converted to fp16 in smem (Vt[d][k pairs]).
// fp16 (not bf16): 4x smaller quantization error, range-safe (see pack_f16).
#define BQ    64
#define BKV   64
#define NT2   (LKV_ / NSPLIT / BKV)   // 64 tiles per CTA
#define LDK   36
#define VTLD  36   // Vt row stride in uint32: PV reads conflict-free

__global__ void __launch_bounds__(128) attn_mma_kernel(
    const float* __restrict__ Q, const float* __restrict__ K,
    const float* __restrict__ V, float* __restrict__ Opart,
    float* __restrict__ Lpart)
{
    __shared__ float    Ks[2][BKV][LDK];
    __shared__ float    Vs[2][BKV][LDK];
    __shared__ uint32_t Vt[2][DH][VTLD];   // [d][kp]: packed f16x2 {V[2kp+1][d], V[2kp][d]}

    const int tid   = threadIdx.x;
    const int wid   = tid >> 5;
    const int lane  = tid & 31;
    const int g     = lane >> 2;
    const int tig   = lane & 3;
    const int q0    = blockIdx.x * BQ;
    const int h     = blockIdx.y;
    const int b     = blockIdx.z / NSPLIT;
    const int split = blockIdx.z % NSPLIT;
    const int qw    = q0 + wid * 16;

    const float* Qb = Q + ((size_t)(b * LQ_ + qw)) * CH + h * DH;
    const float* Kb = K + ((size_t)(b * LKV_ + split * (LKV_ / NSPLIT))) * CH + h * DH;
    const float* Vb = V + ((size_t)(b * LKV_ + split * (LKV_ / NSPLIT))) * CH + h * DH;

    uint32_t aq[4][4];
#pragma unroll
    for (int kc = 0; kc < 4; kc++) {
        const int c0 = kc * 8 + tig;
        aq[kc][0] = f2tf32(Qb[(size_t)g       * CH + c0    ] * QSCALE);
        aq[kc][1] = f2tf32(Qb[(size_t)(g + 8) * CH + c0    ] * QSCALE);
        aq[kc][2] = f2tf32(Qb[(size_t)g       * CH + c0 + 4] * QSCALE);
        aq[kc][3] = f2tf32(Qb[(size_t)(g + 8) * CH + c0 + 4] * QSCALE);
    }

    float oacc[4][4];
#pragma unroll
    for (int i = 0; i < 4; i++)
#pragma unroll
        for (int r = 0; r < 4; r++) oacc[i][r] = 0.f;
    float lrow[2] = {0.f, 0.f};

    const int prow = tid >> 3;
    const int pc   = (tid & 7) * 4;
#define ISSUE_TILE(j, nb) do {                                                     \
    const int _k0 = (j) * BKV;                                                     \
    _Pragma("unroll")                                                              \
    for (int t = 0; t < 4; t++) {                                                  \
        const int rw = prow + t * 16;                                              \
        cpa16(smem_u32(&Ks[nb][rw][pc]), Kb + (size_t)(_k0 + rw) * CH + pc);       \
        cpa16(smem_u32(&Vs[nb][rw][pc]), Vb + (size_t)(_k0 + rw) * CH + pc);       \
    }                                                                              \
    CPA_COMMIT();                                                                  \
} while (0)

    ISSUE_TILE(0, 0);

    for (int j = 0; j < NT2; j++) {
        const int nb = j & 1;
        if (j < NT2 - 1) { ISSUE_TILE(j + 1, (j + 1) & 1); CPA_WAIT(1); }
        else             { CPA_WAIT(0); }
        __syncthreads();   // tile j (Ks,Vs) visible to all warps

        // ---- transpose+convert V: Vs[k][d] fp32 -> Vt[d][kp] packed f16x2 ----
#pragma unroll
        for (int w = 0; w < 8; w++) {
            const int idx = tid + w * 128;          // 0..1023
            const int d   = idx & 31;
            const int kp  = idx >> 5;               // 0..31
            const float e = Vs[nb][2 * kp][d];
            const float o = Vs[nb][2 * kp + 1][d];
            Vt[nb][d][kp] = pack_f16(o, e);
        }

        // ---- S = Q·K^T : per warp m16 x n64, K-dim 32 (tf32) ----
        float sacc[8][4];
#pragma unroll
        for (int n = 0; n < 8; n++)
#pragma unroll
            for (int r = 0; r < 4; r++) sacc[n][r] = 0.f;

#pragma unroll
        for (int nch = 0; nch < 8; nch++) {
            const float* krow = &Ks[nb][nch * 8 + g][0];
#pragma unroll
            for (int kc = 0; kc < 4; kc++) {
                const uint32_t b0 = __float_as_uint(krow[kc * 8 + tig]);
                const uint32_t b1 = __float_as_uint(krow[kc * 8 + tig + 4]);
                mma8(sacc[nch], aq[kc], b0, b1);
            }
        }

        // ---- softmax: p = exp2(s), fixed basis ----
#pragma unroll
        for (int n = 0; n < 8; n++) {
#pragma unroll
            for (int r = 0; r < 4; r++) {
                const float p = fexp2(sacc[n][r]);
                sacc[n][r] = p;
                lrow[r >> 1] += p;
            }
        }
        __syncthreads();   // Vt[nb] writes visible to all warps before PV reads

        // ---- PV (fp16 m16n8k16): A-frags = packed C-frags, no shuffles ----
#pragma unroll
        for (int kc2 = 0; kc2 < 4; kc2++) {
            uint32_t ap[4];
            ap[0] = pack_f16(sacc[2*kc2][1],     sacc[2*kc2][0]);
            ap[1] = pack_f16(sacc[2*kc2][3],     sacc[2*kc2][2]);
            ap[2] = pack_f16(sacc[2*kc2+1][1],   sacc[2*kc2+1][0]);
            ap[3] = pack_f16(sacc[2*kc2+1][3],   sacc[2*kc2+1][2]);
#pragma unroll
            for (int nch = 0; nch < 4; nch++) {
                const uint32_t* vrow = &Vt[nb][nch * 8 + g][0];
                const uint32_t b0 = vrow[8 * kc2 + tig];
                const uint32_t b1 = vrow[8 * kc2 + 4 + tig];
                mma16h(oacc[nch], ap, b0, b1);
            }
        }
        __syncthreads();   // all PV/Vt reads done before next iter's cp.async
    }

    // ---- reduce l across quad; write UNNORMALIZED partials ----
#pragma unroll
    for (int r = 0; r < 2; r++) {
        lrow[r] += __shfl_xor_sync(0xffffffffu, lrow[r], 1);
        lrow[r] += __shfl_xor_sync(0xffffffffu, lrow[r], 2);
    }

    float* Ob = Opart + (size_t)split * (B_ * LQ_ * CH)
              + ((size_t)(b * LQ_ + qw)) * CH + h * DH;
#pragma unroll
    for (int nch = 0; nch < 4; nch++) {
        const int c = nch * 8 + 2 * tig;
        *(float2*)(Ob + (size_t)g       * CH + c) = make_float2(oacc[nch][0], oacc[nch][1]);
        *(float2*)(Ob + (size_t)(g + 8) * CH + c) = make_float2(oacc[nch][2], oacc[nch][3]);
    }
    if (tig == 0) {
        float* Lb = Lpart + (size_t)split * (B_ * LQ_ * HEADS)
                  + ((size_t)(b * LQ_ + qw)) * HEADS + h;
        Lb[(size_t)g       * HEADS] = lrow[0];
        Lb[(size_t)(g + 8) * HEADS] = lrow[1];
    }
}

// ---------------- combine: out = (sum_s O_s) / (sum_s l_s) ----------------
__global__ void __launch_bounds__(256) combine_kernel(
    const float* __restrict__ Opart, const float* __restrict__ Lpart,
    float* __restrict__ out)
{
    const int i = blockIdx.x * 256 + threadIdx.x;   // over B*LQ*CH
    const int row = i >> 8;                          // b*LQ + q
    const int h   = (i & (CH - 1)) >> 5;
    float o = 0.f, l = 0.f;
#pragma unroll
    for (int s = 0; s < NSPLIT; s++) {
        o += Opart[(size_t)s * (B_ * LQ_ * CH) + i];
        l += Lpart[(size_t)s * (B_ * LQ_ * HEADS) + row * HEADS + h];
    }
    out[i] = o / l;
}

// ---------------- launch ----------------
extern "C" void kernel_launch(void* const* d_in, const int* in_sizes, int n_in,
                              void* d_out, int out_size)
{
    const float* hidden = (const float*)d_in[0];
    const float* inputs = (const float*)d_in[1];
    const float* ln1_g  = (const float*)d_in[2];
    const float* ln1_b  = (const float*)d_in[3];
    const float* ln2_g  = (const float*)d_in[4];
    const float* ln2_b  = (const float*)d_in[5];
    const float* Wq     = (const float*)d_in[6];
    const float* bq     = (const float*)d_in[7];
    const float* Wk     = (const float*)d_in[8];
    const float* bk     = (const float*)d_in[9];
    const float* Wv     = (const float*)d_in[10];
    const float* bv     = (const float*)d_in[11];
    float* out = (float*)d_out;

    void *p; float *hsn, *inpn, *q, *k, *v, *wq, *wk, *wv, *op, *lp;
    cudaGetSymbolAddress(&p, g_hsn);  hsn  = (float*)p;
    cudaGetSymbolAddress(&p, g_inpn); inpn = (float*)p;
    cudaGetSymbolAddress(&p, g_q);  q  = (float*)p;
    cudaGetSymbolAddress(&p, g_k);  k  = (float*)p;
    cudaGetSymbolAddress(&p, g_v);  v  = (float*)p;
    cudaGetSymbolAddress(&p, g_wq); wq = (float*)p;
    cudaGetSymbolAddress(&p, g_wk); wk = (float*)p;
    cudaGetSymbolAddress(&p, g_wv); wv = (float*)p;
    cudaGetSymbolAddress(&p, g_opart); op = (float*)p;
    cudaGetSymbolAddress(&p, g_lpart); lp = (float*)p;

    // LayerNorms (tf32-rounded outputs)
    ln_kernel<QDIM> <<<B_ * LQ_,  256>>>(hidden, ln1_g, ln1_b, hsn);
    ln_kernel<KVDIM><<<B_ * LKV_, 256>>>(inputs, ln2_g, ln2_b, inpn);

    // Weight rounding (RNA -> unbiased tf32)
    round_w_kernel<<<(QDIM*CH  + 255) / 256, 256>>>(Wq, wq, QDIM*CH);
    round_w_kernel<<<(KVDIM*CH + 255) / 256, 256>>>(Wk, wk, KVDIM*CH);
    round_w_kernel<<<(KVDIM*CH + 255) / 256, 256>>>(Wv, wv, KVDIM*CH);

    // Single-pass tf32 GEMMs
    gemm_tf32_kernel<<<dim3((B_*LQ_)/GBM,  CH/GBN), 256>>>(hsn,  wq, bq, q, B_*LQ_,  QDIM);
    gemm_tf32_kernel<<<dim3((B_*LKV_)/GBM, CH/GBN), 256>>>(inpn, wk, bk, k, B_*LKV_, KVDIM);
    gemm_tf32_kernel<<<dim3((B_*LKV_)/GBM, CH/GBN), 256>>>(inpn, wv, bv, v, B_*LKV_, KVDIM);

    // Split-KV attention (tf32 S + fp16 PV) + combine
    attn_mma_kernel<<<dim3(LQ_/BQ, HEADS, B_*NSPLIT), 128>>>(q, k, v, op, lp);
    combine_kernel<<<(B_*LQ_*CH) / 256, 256>>>(op, lp, out);
}

// round 17
// speedup vs baseline: 1.3259x; 1.3259x over previous
#include <cuda_runtime.h>
#include <math.h>
#include <stdint.h>

// ---------------- problem constants ----------------
#define B_    4
#define LQ_   512
#define LKV_  8192
#define QDIM  1024
#define KVDIM 512
#define CH    256      // QK_CH == V_CH == 256 (GEMM N)
#define CHW   (CH/2)
#define HEADS 8
#define DH    32
#define QSCALE 0.2550348587f   // (1/sqrt(32)) * log2(e)
#define NSPLIT 2               // KV-axis split for attention

// ---------------- scratch ----------------
__device__ uint32_t g_hsn [B_*LQ_*QDIM/2];    // LN(hidden) fp16 pairs along K
__device__ uint32_t g_inpn[B_*LKV_*KVDIM/2];
__device__ float    g_q  [B_*LQ_*CH];          // fp32 (tf32-exact) for attention
__device__ float    g_k  [B_*LKV_*CH];
__device__ float    g_v  [B_*LKV_*CH];
__device__ uint32_t g_wq [QDIM/2*CH];          // W fp16 pairs along K: [kp][n]
__device__ uint32_t g_wk [KVDIM/2*CH];
__device__ uint32_t g_wv [KVDIM/2*CH];
__device__ float g_opart[NSPLIT*B_*LQ_*CH];
__device__ float g_lpart[NSPLIT*B_*LQ_*HEADS];

// ================= helpers (baseline PTX only) =================
__device__ __forceinline__ uint32_t smem_u32(const void* p){
    uint32_t a; asm("{ .reg .u64 t; cvta.to.shared.u64 t, %1; cvt.u32.u64 %0, t; }" : "=r"(a) : "l"(p)); return a;
}
__device__ __forceinline__ uint32_t f2tf32(float f){
    uint32_t t; asm("cvt.rna.tf32.f32 %0, %1;" : "=r"(t) : "f"(f)); return t;
}
__device__ __forceinline__ float fexp2(float x){
    float y; asm("ex2.approx.ftz.f32 %0, %1;" : "=f"(y) : "f"(x)); return y;
}
// pack two f32 -> f16x2 (RNE): first arg -> upper half (validated R13/14)
__device__ __forceinline__ uint32_t pack_f16(float hi, float lo){
    uint32_t r; asm("cvt.rn.f16x2.f32 %0, %1, %2;" : "=r"(r) : "f"(hi), "f"(lo)); return r;
}
__device__ __forceinline__ void cpa16(uint32_t dst, const void* src){
    asm volatile("cp.async.ca.shared.global [%0], [%1], 16;" :: "r"(dst), "l"(src) : "memory");
}
#define CPA_COMMIT() asm volatile("cp.async.commit_group;" ::: "memory")
#define CPA_WAIT(n)  asm volatile("cp.async.wait_group " #n ";" ::: "memory")

// m16n8k8 tf32 mma: D = A*B + D (A row-major, B col-major)
__device__ __forceinline__ void mma8(float* c, const uint32_t* a, uint32_t b0, uint32_t b1){
    asm volatile("mma.sync.aligned.m16n8k8.row.col.f32.tf32.tf32.f32 "
        "{%0,%1,%2,%3}, {%4,%5,%6,%7}, {%8,%9}, {%0,%1,%2,%3};"
        : "+f"(c[0]), "+f"(c[1]), "+f"(c[2]), "+f"(c[3])
        : "r"(a[0]), "r"(a[1]), "r"(a[2]), "r"(a[3]), "r"(b0), "r"(b1));
}
// m16n8k16 fp16 mma (fp32 accum): D = A*B + D
__device__ __forceinline__ void mma16h(float* c, const uint32_t* a, uint32_t b0, uint32_t b1){
    asm volatile("mma.sync.aligned.m16n8k16.row.col.f32.f16.f16.f32 "
        "{%0,%1,%2,%3}, {%4,%5,%6,%7}, {%8,%9}, {%0,%1,%2,%3};"
        : "+f"(c[0]), "+f"(c[1]), "+f"(c[2]), "+f"(c[3])
        : "r"(a[0]), "r"(a[1]), "r"(a[2]), "r"(a[3]), "r"(b0), "r"(b1));
}

// ---------------- LayerNorm, output packed fp16 pairs (GEMM A operand) ------
template<int N>
__global__ __launch_bounds__(256) void ln_kernel(
    const float* __restrict__ x, const float* __restrict__ g,
    const float* __restrict__ b, uint32_t* __restrict__ yp)
{
    constexpr int T = 256;
    constexpr int PERW = N / (2 * T);
    const int row = blockIdx.x;
    const float2* xr = (const float2*)(x + (size_t)row * N);

    float2 v[PERW];
    float s = 0.f, sq = 0.f;
#pragma unroll
    for (int i = 0; i < PERW; i++) {
        v[i] = xr[threadIdx.x + i * T];
        s  += v[i].x + v[i].y;
        sq += v[i].x * v[i].x + v[i].y * v[i].y;
    }
#pragma unroll
    for (int o = 16; o > 0; o >>= 1) {
        s  += __shfl_xor_sync(0xffffffffu, s,  o);
        sq += __shfl_xor_sync(0xffffffffu, sq, o);
    }
    __shared__ float rs[8], rq[8];
    const int warp = threadIdx.x >> 5, lane = threadIdx.x & 31;
    if (lane == 0) { rs[warp] = s; rq[warp] = sq; }
    __syncthreads();
    if (threadIdx.x == 0) {
        float ts = 0.f, tq = 0.f;
#pragma unroll
        for (int i = 0; i < 8; i++) { ts += rs[i]; tq += rq[i]; }
        rs[0] = ts; rq[0] = tq;
    }
    __syncthreads();
    const float mean = rs[0] * (1.f / N);
    const float var  = rq[0] * (1.f / N) - mean * mean;
    const float rstd = rsqrtf(var + 1e-5f);

    uint32_t* yr = yp + (size_t)row * (N / 2);
    const float2* g2 = (const float2*)g;
    const float2* b2 = (const float2*)b;
#pragma unroll
    for (int i = 0; i < PERW; i++) {
        const int pi = threadIdx.x + i * T;
        const float2 gg = g2[pi], bb = b2[pi];
        const float ye = (v[i].x - mean) * rstd * gg.x + bb.x;
        const float yo = (v[i].y - mean) * rstd * gg.y + bb.y;
        yr[pi] = pack_f16(yo, ye);
    }
}

// ---------------- weight pack: W[K][CH] fp32 -> Wp[K/2][CH] fp16-pair words --
__global__ void pack_w_kernel(const float* __restrict__ w, uint32_t* __restrict__ wp, int nw)
{
    const int i = blockIdx.x * 256 + threadIdx.x;
    if (i < nw) {
        const int kp = i / CH, n = i % CH;
        wp[i] = pack_f16(w[(size_t)(2 * kp + 1) * CH + n], w[(size_t)(2 * kp) * CH + n]);
    }
}

// ---------------- fp16 m16n8k16 GEMM, fp32 (tf32-rounded) output ------------
// CTA 128x128, 8 warps (4x2), warp 32x64, k-step 32 fp16 (16 pair-words).
#define GBM 128
#define GBN 128
#define GBK 32
#define AW  16      // pair-words per row per k-step
#define ALD 20      // A smem stride (words) -> A-frag LDS conflict-free
#define WLD 136     // W smem stride (words) -> B-frag banks 8tig+g, conflict-free
#define ASZ (GBM*ALD)
#define WSZ (AW*WLD)

__global__ void __launch_bounds__(256) gemm_f16_kernel(
    const uint32_t* __restrict__ A,   // [M][K/2] fp16 pairs
    const uint32_t* __restrict__ W,   // [K/2][CH] fp16 pairs
    const float* __restrict__ bias, float* __restrict__ C,  // [M][CH] fp32
    int M, int K)
{
    __shared__ uint32_t sA[2][ASZ];
    __shared__ uint32_t sW[2][WSZ];

    const int KW   = K >> 1;
    const int tid  = threadIdx.x;
    const int wid  = tid >> 5;
    const int lane = tid & 31;
    const int g    = lane >> 2;
    const int tig  = lane & 3;
    const int bm   = blockIdx.x * GBM;
    const int bn   = blockIdx.y * GBN;
    const int wm   = (wid & 3) * 32;
    const int wn   = (wid >> 2) * 64;

#define G_ISSUE(s, nb) do {                                                         \
    const int _kw0 = (s) * AW;                                                      \
    _Pragma("unroll")                                                               \
    for (int i = 0; i < 2; i++) {                                                   \
        const int idx = tid + i * 256;                                              \
        const int ar = idx >> 2, a4 = (idx & 3) * 4;                                \
        cpa16(smem_u32(&sA[nb][ar*ALD + a4]), A + (size_t)(bm+ar)*KW + _kw0 + a4);  \
        const int wr = idx >> 5, wc = (idx & 31) * 4;                               \
        cpa16(smem_u32(&sW[nb][wr*WLD + wc]), W + (size_t)(_kw0+wr)*CH + bn + wc);  \
    }                                                                               \
    CPA_COMMIT();                                                                   \
} while (0)

    float cacc[2][8][4];
#pragma unroll
    for (int i = 0; i < 2; i++)
#pragma unroll
        for (int n = 0; n < 8; n++)
#pragma unroll
            for (int r = 0; r < 4; r++) cacc[i][n][r] = 0.f;

    const int NS = K / GBK;
    G_ISSUE(0, 0);

    for (int s = 0; s < NS; s++) {
        const int nb = s & 1;
        if (s < NS - 1) { G_ISSUE(s + 1, (s + 1) & 1); CPA_WAIT(1); }
        else            { CPA_WAIT(0); }
        __syncthreads();

#pragma unroll
        for (int k8 = 0; k8 < 2; k8++) {
            const int kc = k8 * 8 + tig;
            uint32_t af[2][4];
#pragma unroll
            for (int i = 0; i < 2; i++) {
                const int r0 = (wm + i * 16 + g) * ALD;
                const int r1 = (wm + i * 16 + g + 8) * ALD;
                af[i][0] = sA[nb][r0 + kc];     af[i][1] = sA[nb][r1 + kc];
                af[i][2] = sA[nb][r0 + kc + 4]; af[i][3] = sA[nb][r1 + kc + 4];
            }
#pragma unroll
            for (int nf = 0; nf < 8; nf++) {
                const int n = wn + nf * 8 + g;
                const uint32_t b0 = sW[nb][(k8 * 8 + tig) * WLD + n];
                const uint32_t b1 = sW[nb][(k8 * 8 + tig + 4) * WLD + n];
                mma16h(cacc[0][nf], af[0], b0, b1);
                mma16h(cacc[1][nf], af[1], b0, b1);
            }
        }
        __syncthreads();
    }

    // ---- epilogue: bias, RNA-round to tf32, store fp32 (R14 contract) ----
#pragma unroll
    for (int i = 0; i < 2; i++) {
#pragma unroll
        for (int n = 0; n < 8; n++) {
            const int col = bn + wn + n * 8 + 2 * tig;
            const float b0 = bias[col], b1 = bias[col + 1];
            const int r0 = bm + wm + i * 16 + g;
            float2 w0, w1;
            w0.x = __uint_as_float(f2tf32(cacc[i][n][0] + b0));
            w0.y = __uint_as_float(f2tf32(cacc[i][n][1] + b1));
            w1.x = __uint_as_float(f2tf32(cacc[i][n][2] + b0));
            w1.y = __uint_as_float(f2tf32(cacc[i][n][3] + b1));
            *(float2*)(C + (size_t)r0 * CH + col)       = w0;
            *(float2*)(C + (size_t)(r0 + 8) * CH + col) = w1;
        }
    }
}

// ================= split-KV attention (R14 VERBATIM: tf32 S + fp16 PV) =======
#define BQ    64
#define BKV   64
#define NT2   (LKV_ / NSPLIT / BKV)   // 64 tiles per CTA
#define LDK   36
#define VTLD  36

__global__ void __launch_bounds__(128) attn_mma_kernel(
    const float* __restrict__ Q, const float* __restrict__ K,
    const float* __restrict__ V, float* __restrict__ Opart,
    float* __restrict__ Lpart)
{
    __shared__ float    Ks[2][BKV][LDK];
    __shared__ float    Vs[2][BKV][LDK];
    __shared__ uint32_t Vt[2][DH][VTLD];

    const int tid   = threadIdx.x;
    const int wid   = tid >> 5;
    const int lane  = tid & 31;
    const int g     = lane >> 2;
    const int tig   = lane & 3;
    const int q0    = blockIdx.x * BQ;
    const int h     = blockIdx.y;
    const int b     = blockIdx.z / NSPLIT;
    const int split = blockIdx.z % NSPLIT;
    const int qw    = q0 + wid * 16;

    const float* Qb = Q + ((size_t)(b * LQ_ + qw)) * CH + h * DH;
    const float* Kb = K + ((size_t)(b * LKV_ + split * (LKV_ / NSPLIT))) * CH + h * DH;
    const float* Vb = V + ((size_t)(b * LKV_ + split * (LKV_ / NSPLIT))) * CH + h * DH;

    uint32_t aq[4][4];
#pragma unroll
    for (int kc = 0; kc < 4; kc++) {
        const int c0 = kc * 8 + tig;
        aq[kc][0] = f2tf32(Qb[(size_t)g       * CH + c0    ] * QSCALE);
        aq[kc][1] = f2tf32(Qb[(size_t)(g + 8) * CH + c0    ] * QSCALE);
        aq[kc][2] = f2tf32(Qb[(size_t)g       * CH + c0 + 4] * QSCALE);
        aq[kc][3] = f2tf32(Qb[(size_t)(g + 8) * CH + c0 + 4] * QSCALE);
    }

    float oacc[4][4];
#pragma unroll
    for (int i = 0; i < 4; i++)
#pragma unroll
        for (int r = 0; r < 4; r++) oacc[i][r] = 0.f;
    float lrow[2] = {0.f, 0.f};

    const int prow = tid >> 3;
    const int pc   = (tid & 7) * 4;
#define ISSUE_TILE(j, nb) do {                                                     \
    const int _k0 = (j) * BKV;                                                     \
    _Pragma("unroll")                                                              \
    for (int t = 0; t < 4; t++) {                                                  \
        const int rw = prow + t * 16;                                              \
        cpa16(smem_u32(&Ks[nb][rw][pc]), Kb + (size_t)(_k0 + rw) * CH + pc);       \
        cpa16(smem_u32(&Vs[nb][rw][pc]), Vb + (size_t)(_k0 + rw) * CH + pc);       \
    }                                                                              \
    CPA_COMMIT();                                                                  \
} while (0)

    ISSUE_TILE(0, 0);

    for (int j = 0; j < NT2; j++) {
        const int nb = j & 1;
        if (j < NT2 - 1) { ISSUE_TILE(j + 1, (j + 1) & 1); CPA_WAIT(1); }
        else             { CPA_WAIT(0); }
        __syncthreads();

#pragma unroll
        for (int w = 0; w < 8; w++) {
            const int idx = tid + w * 128;
            const int d   = idx & 31;
            const int kp  = idx >> 5;
            const float e = Vs[nb][2 * kp][d];
            const float o = Vs[nb][2 * kp + 1][d];
            Vt[nb][d][kp] = pack_f16(o, e);
        }

        float sacc[8][4];
#pragma unroll
        for (int n = 0; n < 8; n++)
#pragma unroll
            for (int r = 0; r < 4; r++) sacc[n][r] = 0.f;

#pragma unroll
        for (int nch = 0; nch < 8; nch++) {
            const float* krow = &Ks[nb][nch * 8 + g][0];
#pragma unroll
            for (int kc = 0; kc < 4; kc++) {
                const uint32_t b0 = __float_as_uint(krow[kc * 8 + tig]);
                const uint32_t b1 = __float_as_uint(krow[kc * 8 + tig + 4]);
                mma8(sacc[nch], aq[kc], b0, b1);
            }
        }

#pragma unroll
        for (int n = 0; n < 8; n++) {
#pragma unroll
            for (int r = 0; r < 4; r++) {
                const float p = fexp2(sacc[n][r]);
                sacc[n][r] = p;
                lrow[r >> 1] += p;
            }
        }
        __syncthreads();

#pragma unroll
        for (int kc2 = 0; kc2 < 4; kc2++) {
            uint32_t ap[4];
            ap[0] = pack_f16(sacc[2*kc2][1],     sacc[2*kc2][0]);
            ap[1] = pack_f16(sacc[2*kc2][3],     sacc[2*kc2][2]);
            ap[2] = pack_f16(sacc[2*kc2+1][1],   sacc[2*kc2+1][0]);
            ap[3] = pack_f16(sacc[2*kc2+1][3],   sacc[2*kc2+1][2]);
#pragma unroll
            for (int nch = 0; nch < 4; nch++) {
                const uint32_t* vrow = &Vt[nb][nch * 8 + g][0];
                const uint32_t b0 = vrow[8 * kc2 + tig];
                const uint32_t b1 = vrow[8 * kc2 + 4 + tig];
                mma16h(oacc[nch], ap, b0, b1);
            }
        }
        __syncthreads();
    }

#pragma unroll
    for (int r = 0; r < 2; r++) {
        lrow[r] += __shfl_xor_sync(0xffffffffu, lrow[r], 1);
        lrow[r] += __shfl_xor_sync(0xffffffffu, lrow[r], 2);
    }

    float* Ob = Opart + (size_t)split * (B_ * LQ_ * CH)
              + ((size_t)(b * LQ_ + qw)) * CH + h * DH;
#pragma unroll
    for (int nch = 0; nch < 4; nch++) {
        const int c = nch * 8 + 2 * tig;
        *(float2*)(Ob + (size_t)g       * CH + c) = make_float2(oacc[nch][0], oacc[nch][1]);
        *(float2*)(Ob + (size_t)(g + 8) * CH + c) = make_float2(oacc[nch][2], oacc[nch][3]);
    }
    if (tig == 0) {
        float* Lb = Lpart + (size_t)split * (B_ * LQ_ * HEADS)
                  + ((size_t)(b * LQ_ + qw)) * HEADS + h;
        Lb[(size_t)g       * HEADS] = lrow[0];
        Lb[(size_t)(g + 8) * HEADS] = lrow[1];
    }
}

// ---------------- combine: out = (sum_s O_s) / (sum_s l_s) ----------------
__global__ void __launch_bounds__(256) combine_kernel(
    const float* __restrict__ Opart, const float* __restrict__ Lpart,
    float* __restrict__ out)
{
    const int i = blockIdx.x * 256 + threadIdx.x;
    const int row = i >> 8;
    const int h   = (i & (CH - 1)) >> 5;
    float o = 0.f, l = 0.f;
#pragma unroll
    for (int s = 0; s < NSPLIT; s++) {
        o += Opart[(size_t)s * (B_ * LQ_ * CH) + i];
        l += Lpart[(size_t)s * (B_ * LQ_ * HEADS) + row * HEADS + h];
    }
    out[i] = o / l;
}

// ---------------- launch ----------------
extern "C" void kernel_launch(void* const* d_in, const int* in_sizes, int n_in,
                              void* d_out, int out_size)
{
    const float* hidden = (const float*)d_in[0];
    const float* inputs = (const float*)d_in[1];
    const float* ln1_g  = (const float*)d_in[2];
    const float* ln1_b  = (const float*)d_in[3];
    const float* ln2_g  = (const float*)d_in[4];
    const float* ln2_b  = (const float*)d_in[5];
    const float* Wq     = (const float*)d_in[6];
    const float* bq     = (const float*)d_in[7];
    const float* Wk     = (const float*)d_in[8];
    const float* bk     = (const float*)d_in[9];
    const float* Wv     = (const float*)d_in[10];
    const float* bv     = (const float*)d_in[11];
    float* out = (float*)d_out;

    void *p; uint32_t *hsn, *inpn, *wq, *wk, *wv;
    float *q, *k, *v, *op, *lp;
    cudaGetSymbolAddress(&p, g_hsn);  hsn  = (uint32_t*)p;
    cudaGetSymbolAddress(&p, g_inpn); inpn = (uint32_t*)p;
    cudaGetSymbolAddress(&p, g_q);  q  = (float*)p;
    cudaGetSymbolAddress(&p, g_k);  k  = (float*)p;
    cudaGetSymbolAddress(&p, g_v);  v  = (float*)p;
    cudaGetSymbolAddress(&p, g_wq); wq = (uint32_t*)p;
    cudaGetSymbolAddress(&p, g_wk); wk = (uint32_t*)p;
    cudaGetSymbolAddress(&p, g_wv); wv = (uint32_t*)p;
    cudaGetSymbolAddress(&p, g_opart); op = (float*)p;
    cudaGetSymbolAddress(&p, g_lpart); lp = (float*)p;

    // LayerNorms (packed fp16-pair outputs for GEMM)
    ln_kernel<QDIM> <<<B_ * LQ_,  256>>>(hidden, ln1_g, ln1_b, hsn);
    ln_kernel<KVDIM><<<B_ * LKV_, 256>>>(inputs, ln2_g, ln2_b, inpn);

    // Weight packing (fp32 -> fp16 pairs along K)
    pack_w_kernel<<<(QDIM/2*CH  + 255) / 256, 256>>>(Wq, wq, QDIM/2*CH);
    pack_w_kernel<<<(KVDIM/2*CH + 255) / 256, 256>>>(Wk, wk, KVDIM/2*CH);
    pack_w_kernel<<<(KVDIM/2*CH + 255) / 256, 256>>>(Wv, wv, KVDIM/2*CH);

    // fp16 m16n8k16 GEMMs, fp32 tf32-rounded outputs (R14 attention contract)
    gemm_f16_kernel<<<dim3((B_*LQ_)/GBM,  CH/GBN), 256>>>(hsn,  wq, bq, q, B_*LQ_,  QDIM);
    gemm_f16_kernel<<<dim3((B_*LKV_)/GBM, CH/GBN), 256>>>(inpn, wk, bk, k, B_*LKV_, KVDIM);
    gemm_f16_kernel<<<dim3((B_*LKV_)/GBM, CH/GBN), 256>>>(inpn, wv, bv, v, B_*LKV_, KVDIM);

    // Split-KV attention (R14 verbatim) + combine
    attn_mma_kernel<<<dim3(LQ_/BQ, HEADS, B_*NSPLIT), 128>>>(q, k, v, op, lp);
    combine_kernel<<<(B_*LQ_*CH) / 256, 256>>>(op, lp, out);
}